// round 6
// baseline (speedup 1.0000x reference)
#include <cuda_runtime.h>
#include <cuda_bf16.h>

// Cosine similarity per row: out[i] = dot(q_i, d_i) / (||q_i|| * ||d_i||)
// N = 262144 rows, D = 256 fp32.
// One warp per TWO ADJACENT rows (contiguous 2KB window per tensor per warp),
// 8 front-batched LDG.128 (MLP_p1 = 8), classic grid, streaming cache hints.

#define D_DIM 256
#define D4 (D_DIM / 4)
#define THREADS_PER_BLOCK 256
#define WARPS_PER_BLOCK (THREADS_PER_BLOCK / 32)
#define ROWS_PER_WARP 2
#define ROWS_PER_BLOCK (WARPS_PER_BLOCK * ROWS_PER_WARP)

__global__ __launch_bounds__(THREADS_PER_BLOCK)
void cosine_sim_kernel(const float4* __restrict__ q4,
                       const float4* __restrict__ d4,
                       float* __restrict__ out,
                       int n_rows) {
    const int warp_id = (blockIdx.x * WARPS_PER_BLOCK) + (threadIdx.x >> 5);
    const int lane = threadIdx.x & 31;
    const int r0 = warp_id * ROWS_PER_WARP;        // adjacent pair: r0, r0+1
    if (r0 >= n_rows) return;

    // Contiguous 128-float4 (2KB) window per tensor covering rows r0, r0+1.
    const float4* qr = q4 + (size_t)r0 * D4;
    const float4* dr = d4 + (size_t)r0 * D4;

    // Front-batch all 8 LDG.128, interleaving q and d streams.
    // Row r0 spans float4 [0,64); row r0+1 spans [64,128).
    float4 qa0 = __ldcs(qr + lane);
    float4 da0 = __ldcs(dr + lane);
    float4 qb0 = __ldcs(qr + lane + 32);
    float4 db0 = __ldcs(dr + lane + 32);
    float4 qa1 = __ldcs(qr + lane + 64);
    float4 da1 = __ldcs(dr + lane + 64);
    float4 qb1 = __ldcs(qr + lane + 96);
    float4 db1 = __ldcs(dr + lane + 96);

    float dot0 = qa0.x * da0.x + qa0.y * da0.y + qa0.z * da0.z + qa0.w * da0.w
               + qb0.x * db0.x + qb0.y * db0.y + qb0.z * db0.z + qb0.w * db0.w;
    float qq0  = qa0.x * qa0.x + qa0.y * qa0.y + qa0.z * qa0.z + qa0.w * qa0.w
               + qb0.x * qb0.x + qb0.y * qb0.y + qb0.z * qb0.z + qb0.w * qb0.w;
    float dd0  = da0.x * da0.x + da0.y * da0.y + da0.z * da0.z + da0.w * da0.w
               + db0.x * db0.x + db0.y * db0.y + db0.z * db0.z + db0.w * db0.w;

    float dot1 = qa1.x * da1.x + qa1.y * da1.y + qa1.z * da1.z + qa1.w * da1.w
               + qb1.x * db1.x + qb1.y * db1.y + qb1.z * db1.z + qb1.w * db1.w;
    float qq1  = qa1.x * qa1.x + qa1.y * qa1.y + qa1.z * qa1.z + qa1.w * qa1.w
               + qb1.x * qb1.x + qb1.y * qb1.y + qb1.z * qb1.z + qb1.w * qb1.w;
    float dd1  = da1.x * da1.x + da1.y * da1.y + da1.z * da1.z + da1.w * da1.w
               + db1.x * db1.x + db1.y * db1.y + db1.z * db1.z + db1.w * db1.w;

    // Six independent butterfly chains, interleaved for ILP.
    #pragma unroll
    for (int off = 16; off > 0; off >>= 1) {
        dot0 += __shfl_xor_sync(0xFFFFFFFFu, dot0, off);
        dot1 += __shfl_xor_sync(0xFFFFFFFFu, dot1, off);
        qq0  += __shfl_xor_sync(0xFFFFFFFFu, qq0,  off);
        qq1  += __shfl_xor_sync(0xFFFFFFFFu, qq1,  off);
        dd0  += __shfl_xor_sync(0xFFFFFFFFu, dd0,  off);
        dd1  += __shfl_xor_sync(0xFFFFFFFFu, dd1,  off);
    }

    if (lane == 0) {
        __stcs(out + r0, dot0 * rsqrtf(qq0 * dd0));
        if (r0 + 1 < n_rows)
            __stcs(out + r0 + 1, dot1 * rsqrtf(qq1 * dd1));
    }
}

extern "C" void kernel_launch(void* const* d_in, const int* in_sizes, int n_in,
                              void* d_out, int out_size) {
    const float4* q = (const float4*)d_in[0];
    const float4* d = (const float4*)d_in[1];
    float* out = (float*)d_out;

    const int n_rows = in_sizes[0] / D_DIM;
    const int blocks = (n_rows + ROWS_PER_BLOCK - 1) / ROWS_PER_BLOCK;

    cosine_sim_kernel<<<blocks, THREADS_PER_BLOCK>>>(q, d, out, n_rows);
}